// round 3
// baseline (speedup 1.0000x reference)
#include <cuda_runtime.h>
#include <cuda_bf16.h>

#define NV 20000
#define EN 640000
#define FD 256
#define CD 16

// ---------------- scratch (device globals; no allocation allowed) ----------
__device__ int   g_deg[NV];
__device__ int   g_off[NV + 1];
__device__ int   g_cur[NV];
__device__ int   g_srcs[EN];
__device__ float g_w1[256 * 512];    // [K=256][N=512]  = [W1l | W1r]
__device__ float g_w2[256 * 32];     // [K=256][N=32]   = [W2l@Wc | W2r@Wc]
__device__ float g_bp[16];           // b2@Wc + bc
__device__ float g_y[NV * 256];      // x @ W1l
__device__ float g_r[NV * 256];      // x @ W1r
__device__ float g_h[NV * 256];      // relu(mean(y) + r + b1)
__device__ float g_qs[NV * 32];      // [h@W2lWc | h@W2rWc]

// ---------------- CSR build ------------------------------------------------
__global__ void k_zero()
{
    int i = blockIdx.x * blockDim.x + threadIdx.x;
    if (i < NV) g_deg[i] = 0;
}

// edge_index is int32 [2, E] (JAX x64 disabled -> int64 request yields int32)
__global__ void k_hist(const int* __restrict__ ei)
{
    int e = blockIdx.x * blockDim.x + threadIdx.x;
    if (e < EN) {
        unsigned dst = (unsigned)ei[EN + e];
        if (dst < NV) atomicAdd(&g_deg[dst], 1);
    }
}

__global__ void k_scan()
{
    __shared__ int part[1024];
    const int CH = 20;                       // 1024*20 >= 20000
    int t = threadIdx.x;
    int base = t * CH;
    int s = 0;
#pragma unroll
    for (int j = 0; j < CH; ++j) {
        int idx = base + j;
        if (idx < NV) s += g_deg[idx];
    }
    part[t] = s;
    __syncthreads();
    for (int off = 1; off < 1024; off <<= 1) {
        int v = 0;
        if (t >= off) v = part[t - off];
        __syncthreads();
        if (t >= off) part[t] += v;
        __syncthreads();
    }
    int run = (t == 0) ? 0 : part[t - 1];
#pragma unroll
    for (int j = 0; j < CH; ++j) {
        int idx = base + j;
        if (idx < NV) {
            g_off[idx] = run;
            g_cur[idx] = run;
            run += g_deg[idx];
        }
    }
    if (t == 0) g_off[NV] = EN;
}

__global__ void k_scatter(const int* __restrict__ ei)
{
    int e = blockIdx.x * blockDim.x + threadIdx.x;
    if (e < EN) {
        unsigned src = (unsigned)ei[e];
        unsigned dst = (unsigned)ei[EN + e];
        if (dst < NV && src < NV) {
            int pos = atomicAdd(&g_cur[dst], 1);
            g_srcs[pos] = (int)src;
        }
    }
}

// ---------------- weight prep ----------------------------------------------
__global__ void k_prepw1(const float* __restrict__ W1l, const float* __restrict__ W1r)
{
    int i = blockIdx.x * blockDim.x + threadIdx.x;   // 256*512
    if (i < 256 * 512) {
        int k = i >> 9, n = i & 511;
        g_w1[i] = (n < 256) ? W1l[k * 256 + n] : W1r[k * 256 + (n - 256)];
    }
}

__global__ void k_prepw2(const float* __restrict__ W2l, const float* __restrict__ W2r,
                         const float* __restrict__ Wc)
{
    int i = blockIdx.x * blockDim.x + threadIdx.x;   // 256*32
    if (i < 256 * 32) {
        int k = i >> 5, n = i & 31;
        const float* W = (n < 16) ? W2l : W2r;
        int c = n & 15;
        float acc = 0.f;
#pragma unroll 8
        for (int m = 0; m < 256; ++m)
            acc += W[k * 256 + m] * Wc[m * 16 + c];
        g_w2[i] = acc;
    }
}

__global__ void k_prepb(const float* __restrict__ b2, const float* __restrict__ Wc,
                        const float* __restrict__ bc)
{
    int c = threadIdx.x;
    if (c < 16) {
        float acc = bc[c];
        for (int m = 0; m < 256; ++m) acc += b2[m] * Wc[m * 16 + c];
        g_bp[c] = acc;
    }
}

// ---------------- SGEMM1: [y|r] = x @ g_w1  (M=20000, N=512, K=256) --------
__global__ __launch_bounds__(256) void k_gemm1(const float* __restrict__ A)
{
    __shared__ float As[2][8][128];
    __shared__ float Bs[2][8][128];

    int tid = threadIdx.x;
    int bx = blockIdx.x;             // N tile (0..3)
    int by = blockIdx.y;             // M tile (0..156)

    int arow = tid >> 1;             // 0..127
    int acol = (tid & 1) * 4;        // 0 or 4
    int brow = tid >> 5;             // 0..7
    int bcol = (tid & 31) * 4;       // 0..124

    int grow = by * 128 + arow;
    if (grow >= NV) grow = NV - 1;
    const float* Aptr = A + (long)grow * 256 + acol;
    const float* Bptr = g_w1 + (long)brow * 512 + bx * 128 + bcol;

    int tx = tid & 15, ty = tid >> 4;

    float acc[8][8];
#pragma unroll
    for (int i = 0; i < 8; ++i)
#pragma unroll
        for (int j = 0; j < 8; ++j) acc[i][j] = 0.f;

    // prime buffer 0
    {
        float4 pa = *(const float4*)(Aptr);
        float4 pb = *(const float4*)(Bptr);
        As[0][acol + 0][arow] = pa.x;
        As[0][acol + 1][arow] = pa.y;
        As[0][acol + 2][arow] = pa.z;
        As[0][acol + 3][arow] = pa.w;
        *(float4*)&Bs[0][brow][bcol] = pb;
    }
    __syncthreads();

    int cur = 0;
#pragma unroll 1
    for (int kt = 0; kt < 32; ++kt) {
        float4 pa, pb;
        if (kt < 31) {
            pa = *(const float4*)(Aptr + (kt + 1) * 8);
            pb = *(const float4*)(Bptr + (size_t)(kt + 1) * 8 * 512);
        }
        float af[8], bf[8];
#pragma unroll
        for (int kk = 0; kk < 8; ++kk) {
            *(float4*)(af)     = *(const float4*)&As[cur][kk][ty * 8];
            *(float4*)(af + 4) = *(const float4*)&As[cur][kk][ty * 8 + 4];
            *(float4*)(bf)     = *(const float4*)&Bs[cur][kk][tx * 8];
            *(float4*)(bf + 4) = *(const float4*)&Bs[cur][kk][tx * 8 + 4];
#pragma unroll
            for (int i = 0; i < 8; ++i)
#pragma unroll
                for (int j = 0; j < 8; ++j)
                    acc[i][j] += af[i] * bf[j];
        }
        if (kt < 31) {
            int nxt = cur ^ 1;
            __syncthreads();
            As[nxt][acol + 0][arow] = pa.x;
            As[nxt][acol + 1][arow] = pa.y;
            As[nxt][acol + 2][arow] = pa.z;
            As[nxt][acol + 3][arow] = pa.w;
            *(float4*)&Bs[nxt][brow][bcol] = pb;
            __syncthreads();
            cur = nxt;
        }
    }

    int rbase = by * 128 + ty * 8;
    int cbase = bx * 128 + tx * 8;
#pragma unroll
    for (int i = 0; i < 8; ++i) {
        int r = rbase + i;
        if (r < NV) {
            if (cbase < 256) {
#pragma unroll
                for (int j = 0; j < 8; ++j)
                    g_y[(long)r * 256 + cbase + j] = acc[i][j];
            } else {
#pragma unroll
                for (int j = 0; j < 8; ++j)
                    g_r[(long)r * 256 + cbase - 256 + j] = acc[i][j];
            }
        }
    }
}

// ---------------- agg1 + relu: h = relu(mean_j y[j] + r + b1) ---------------
__global__ __launch_bounds__(256) void k_agg1(const float* __restrict__ b1)
{
    int i = blockIdx.x;
    int t = threadIdx.x;
    int beg = g_off[i], end = g_off[i + 1];

    float a0 = 0.f, a1 = 0.f, a2 = 0.f, a3 = 0.f;
    int e = beg;
    for (; e + 4 <= end; e += 4) {
        int s0 = g_srcs[e + 0];
        int s1 = g_srcs[e + 1];
        int s2 = g_srcs[e + 2];
        int s3 = g_srcs[e + 3];
        a0 += g_y[(long)s0 * 256 + t];
        a1 += g_y[(long)s1 * 256 + t];
        a2 += g_y[(long)s2 * 256 + t];
        a3 += g_y[(long)s3 * 256 + t];
    }
    for (; e < end; ++e)
        a0 += g_y[(long)g_srcs[e] * 256 + t];

    float sum = (a0 + a1) + (a2 + a3);
    int deg = end - beg;
    float inv = 1.0f / (float)(deg > 0 ? deg : 1);
    float v = sum * inv + g_r[(long)i * 256 + t] + b1[t];
    g_h[(long)i * 256 + t] = v > 0.f ? v : 0.f;
}

// ---------------- GEMM2: g_qs = h @ g_w2  (M=20000, N=32, K=256) ------------
__global__ __launch_bounds__(256) void k_gemm2()
{
    __shared__ float w2s[256 * 32];   // 32KB
    __shared__ float hs[64 * 32];     // 8KB
    int t = threadIdx.x;
    for (int i = t; i < 256 * 32; i += 256) w2s[i] = g_w2[i];

    int rowbase = blockIdx.x * 64;
    int c = t & 31, rg = t >> 5;      // col, row-group
    float acc[8];
#pragma unroll
    for (int r = 0; r < 8; ++r) acc[r] = 0.f;

    for (int k0 = 0; k0 < 256; k0 += 32) {
        __syncthreads();
        for (int i = t; i < 64 * 32; i += 256) {
            int rr = i >> 5, kk = i & 31;
            int row = rowbase + rr;
            if (row >= NV) row = NV - 1;
            hs[i] = g_h[(long)row * 256 + k0 + kk];
        }
        __syncthreads();
#pragma unroll
        for (int kk = 0; kk < 32; ++kk) {
            float w = w2s[(k0 + kk) * 32 + c];
#pragma unroll
            for (int r = 0; r < 8; ++r)
                acc[r] += hs[(rg + 8 * r) * 32 + kk] * w;
        }
    }
#pragma unroll
    for (int r = 0; r < 8; ++r) {
        int row = rowbase + rg + 8 * r;
        if (row < NV) g_qs[(long)row * 32 + c] = acc[r];
    }
}

// ---------------- out: mean_j q[j] + s + b' --------------------------------
__global__ __launch_bounds__(256) void k_out(float* __restrict__ out)
{
    int t = threadIdx.x;
    int slot = t >> 4;
    int c = t & 15;
    int i = blockIdx.x * 16 + slot;
    if (i >= NV) return;
    int beg = g_off[i], end = g_off[i + 1];
    float acc = 0.f;
    for (int e = beg; e < end; ++e) {
        int s = g_srcs[e];
        acc += g_qs[(long)s * 32 + c];
    }
    int deg = end - beg;
    float inv = 1.0f / (float)(deg > 0 ? deg : 1);
    out[(long)i * 16 + c] = acc * inv + g_qs[(long)i * 32 + 16 + c] + g_bp[c];
}

// ---------------- launch ----------------------------------------------------
extern "C" void kernel_launch(void* const* d_in, const int* in_sizes, int n_in,
                              void* d_out, int out_size)
{
    const float* x   = (const float*)d_in[0];
    const int*   ei  = (const int*)d_in[1];   // int32 [2,E] (JAX default x64 off)
    const float* W1l = (const float*)d_in[2];
    const float* b1  = (const float*)d_in[3];
    const float* W1r = (const float*)d_in[4];
    const float* W2l = (const float*)d_in[5];
    const float* b2  = (const float*)d_in[6];
    const float* W2r = (const float*)d_in[7];
    const float* Wc  = (const float*)d_in[8];
    const float* bc  = (const float*)d_in[9];
    float* out = (float*)d_out;

    // CSR build
    k_zero<<<(NV + 255) / 256, 256>>>();
    k_hist<<<(EN + 255) / 256, 256>>>(ei);
    k_scan<<<1, 1024>>>();
    k_scatter<<<(EN + 255) / 256, 256>>>(ei);

    // weight prep
    k_prepw1<<<(256 * 512) / 256, 256>>>(W1l, W1r);
    k_prepw2<<<(256 * 32) / 256, 256>>>(W2l, W2r, Wc);
    k_prepb<<<1, 16>>>(b2, Wc, bc);

    // layer 1
    k_gemm1<<<dim3(4, 157), 256>>>(x);
    k_agg1<<<NV, 256>>>(b1);

    // layer 2 (folded with classifier)
    k_gemm2<<<(NV + 63) / 64, 256>>>();
    k_out<<<(NV + 15) / 16, 256>>>(out);
}

// round 8
// speedup vs baseline: 1.0978x; 1.0978x over previous
#include <cuda_runtime.h>
#include <cuda_bf16.h>
#include <mma.h>
#include <cstdint>

using namespace nvcuda;

#define NV  20000
#define NVP 20096            // padded rows (multiple of 128) for unmasked wmma ld/st
#define EN  640000

// ---------------- scratch (device globals; no allocation allowed) ----------
__device__ int   g_deg[NV];
__device__ int   g_off[NV + 1];
__device__ int   g_cur[NV];
__device__ int   g_srcs[EN];
__device__ float g_w2[256 * 32];     // [K=256][N=32] = [W2l@Wc | W2r@Wc]
__device__ float g_bp[16];           // b2@Wc + bc
__device__ float g_y[NVP * 256];     // x @ W1l   (padded)
__device__ float g_r[NVP * 256];     // x @ W1r   (padded)
__device__ float g_h[NV * 256];      // relu(mean(y) + r + b1)
__device__ float g_qs[NV * 32];      // [h@W2lWc | h@W2rWc]

__device__ __nv_bfloat16 g_xh[NVP * 256];    // bf16 hi of x (pad rows are zero-init)
__device__ __nv_bfloat16 g_xl[NVP * 256];    // bf16 lo of x
__device__ __nv_bfloat16 g_whT[512 * 256];   // [N=512][K=256] bf16 hi of [W1l|W1r]
__device__ __nv_bfloat16 g_wlT[512 * 256];   // bf16 lo

// ---------------- split / weight prep ---------------------------------------
__global__ void k_split(const float* __restrict__ x)
{
    int i = blockIdx.x * blockDim.x + threadIdx.x;
    if (i < NV * 256) {
        float v = x[i];
        __nv_bfloat16 h = __float2bfloat16(v);
        g_xh[i] = h;
        g_xl[i] = __float2bfloat16(v - __bfloat162float(h));
    }
}

__global__ void k_prepwT(const float* __restrict__ W1l, const float* __restrict__ W1r)
{
    int i = blockIdx.x * blockDim.x + threadIdx.x;   // 512*256
    if (i < 512 * 256) {
        int n = i >> 8, k = i & 255;
        float w = (n < 256) ? W1l[k * 256 + n] : W1r[k * 256 + (n - 256)];
        __nv_bfloat16 h = __float2bfloat16(w);
        g_whT[i] = h;
        g_wlT[i] = __float2bfloat16(w - __bfloat162float(h));
    }
}

__global__ void k_prepw2(const float* __restrict__ W2l, const float* __restrict__ W2r,
                         const float* __restrict__ Wc)
{
    int i = blockIdx.x * blockDim.x + threadIdx.x;   // 256*32
    if (i < 256 * 32) {
        int k = i >> 5, n = i & 31;
        const float* W = (n < 16) ? W2l : W2r;
        int c = n & 15;
        float acc = 0.f;
#pragma unroll 8
        for (int m = 0; m < 256; ++m)
            acc += W[k * 256 + m] * Wc[m * 16 + c];
        g_w2[i] = acc;
    }
}

__global__ void k_prepb(const float* __restrict__ b2, const float* __restrict__ Wc,
                        const float* __restrict__ bc)
{
    int c = threadIdx.x;
    if (c < 16) {
        float acc = bc[c];
        for (int m = 0; m < 256; ++m) acc += b2[m] * Wc[m * 16 + c];
        g_bp[c] = acc;
    }
}

// ---------------- CSR build ------------------------------------------------
__global__ void k_zero()
{
    int i = blockIdx.x * blockDim.x + threadIdx.x;
    if (i < NV) g_deg[i] = 0;
}

__global__ void k_hist(const int* __restrict__ ei)
{
    int e = blockIdx.x * blockDim.x + threadIdx.x;
    if (e < EN) {
        unsigned dst = (unsigned)ei[EN + e];
        if (dst < NV) atomicAdd(&g_deg[dst], 1);
    }
}

__global__ void k_scan()
{
    __shared__ int part[1024];
    const int CH = 20;
    int t = threadIdx.x;
    int base = t * CH;
    int s = 0;
#pragma unroll
    for (int j = 0; j < CH; ++j) {
        int idx = base + j;
        if (idx < NV) s += g_deg[idx];
    }
    part[t] = s;
    __syncthreads();
    for (int off = 1; off < 1024; off <<= 1) {
        int v = 0;
        if (t >= off) v = part[t - off];
        __syncthreads();
        if (t >= off) part[t] += v;
        __syncthreads();
    }
    int run = (t == 0) ? 0 : part[t - 1];
#pragma unroll
    for (int j = 0; j < CH; ++j) {
        int idx = base + j;
        if (idx < NV) {
            g_off[idx] = run;
            g_cur[idx] = run;
            run += g_deg[idx];
        }
    }
    if (t == 0) g_off[NV] = EN;
}

__global__ void k_scatter(const int* __restrict__ ei)
{
    int e = blockIdx.x * blockDim.x + threadIdx.x;
    if (e < EN) {
        unsigned src = (unsigned)ei[e];
        unsigned dst = (unsigned)ei[EN + e];
        if (dst < NV && src < NV) {
            int pos = atomicAdd(&g_cur[dst], 1);
            g_srcs[pos] = (int)src;
        }
    }
}

// ---------------- wmma GEMM1: [y|r] = x @ [W1l|W1r] -------------------------
// Split-precision bf16: y = xh@wh + xl@wh + xh@wl, fp32 accumulate (HMMA).
// CTA tile M=128 x N=64; 8 warps stacked in M (warp tile 16x64).
// B tile (64x256 bf16) staged in STATIC smem, LDB=264 pad; A direct from L2.
#define LDB 264
__global__ __launch_bounds__(256) void k_gemm1_wmma()
{
    __shared__ __nv_bfloat16 bs[64 * LDB];   // 33792 bytes (static, <48KB)

    int tid = threadIdx.x;
    int wid = tid >> 5;
    int bx = blockIdx.x;                     // N tile 0..7
    int by = blockIdx.y;                     // M tile 0..156
    int nbase = bx * 64;
    int row = by * 128 + wid * 16;

    wmma::fragment<wmma::accumulator, 16, 16, 16, float> acc[4];
#pragma unroll
    for (int j = 0; j < 4; ++j) wmma::fill_fragment(acc[j], 0.0f);

    wmma::fragment<wmma::matrix_a, 16, 16, 16, __nv_bfloat16, wmma::row_major> af;
    wmma::fragment<wmma::matrix_b, 16, 16, 16, __nv_bfloat16, wmma::col_major> bf;

#pragma unroll 1
    for (int seg = 0; seg < 3; ++seg) {
        const __nv_bfloat16* Asrc = (seg == 1) ? g_xl : g_xh;
        const __nv_bfloat16* Bsrc = (seg == 2) ? g_wlT : g_whT;

        __syncthreads();   // buffer reuse barrier
        // stage B tile: 64 rows (out features) x 256 bf16
        for (int i = tid; i < 64 * 32; i += 256) {
            int r = i >> 5, c = i & 31;
            *(uint4*)&bs[r * LDB + c * 8] =
                *(const uint4*)&Bsrc[(size_t)(nbase + r) * 256 + c * 8];
        }
        __syncthreads();

#pragma unroll 4
        for (int k0 = 0; k0 < 256; k0 += 16) {
            wmma::load_matrix_sync(af, Asrc + (size_t)row * 256 + k0, 256);
#pragma unroll
            for (int j = 0; j < 4; ++j) {
                wmma::load_matrix_sync(bf, bs + (j * 16) * LDB + k0, LDB);
                wmma::mma_sync(acc[j], af, bf, acc[j]);
            }
        }
    }

    float* dstbase = (bx < 4) ? (g_y + (size_t)row * 256 + nbase)
                              : (g_r + (size_t)row * 256 + (nbase - 256));
#pragma unroll
    for (int j = 0; j < 4; ++j)
        wmma::store_matrix_sync(dstbase + j * 16, acc[j], 256, wmma::mem_row_major);
}

// ---------------- agg1 + relu: h = relu(mean_j y[j] + r + b1) ---------------
__global__ __launch_bounds__(256) void k_agg1(const float* __restrict__ b1)
{
    int i = blockIdx.x;
    int t = threadIdx.x;
    int beg = g_off[i], end = g_off[i + 1];

    float a0 = 0.f, a1 = 0.f, a2 = 0.f, a3 = 0.f;
    int e = beg;
    for (; e + 4 <= end; e += 4) {
        int s0 = g_srcs[e + 0];
        int s1 = g_srcs[e + 1];
        int s2 = g_srcs[e + 2];
        int s3 = g_srcs[e + 3];
        a0 += g_y[(size_t)s0 * 256 + t];
        a1 += g_y[(size_t)s1 * 256 + t];
        a2 += g_y[(size_t)s2 * 256 + t];
        a3 += g_y[(size_t)s3 * 256 + t];
    }
    for (; e < end; ++e)
        a0 += g_y[(size_t)g_srcs[e] * 256 + t];

    float sum = (a0 + a1) + (a2 + a3);
    int deg = end - beg;
    float inv = 1.0f / (float)(deg > 0 ? deg : 1);
    float v = sum * inv + g_r[(size_t)i * 256 + t] + b1[t];
    g_h[(size_t)i * 256 + t] = v > 0.f ? v : 0.f;
}

// ---------------- GEMM2: g_qs = h @ g_w2  (M=20000, N=32, K=256) ------------
__global__ __launch_bounds__(256) void k_gemm2()
{
    __shared__ float w2s[256 * 32];
    __shared__ float hs[64 * 32];
    int t = threadIdx.x;
    for (int i = t; i < 256 * 32; i += 256) w2s[i] = g_w2[i];

    int rowbase = blockIdx.x * 64;
    int c = t & 31, rg = t >> 5;
    float acc[8];
#pragma unroll
    for (int r = 0; r < 8; ++r) acc[r] = 0.f;

    for (int k0 = 0; k0 < 256; k0 += 32) {
        __syncthreads();
        for (int i = t; i < 64 * 32; i += 256) {
            int rr = i >> 5, kk = i & 31;
            int rw = rowbase + rr;
            if (rw >= NV) rw = NV - 1;
            hs[i] = g_h[(size_t)rw * 256 + k0 + kk];
        }
        __syncthreads();
#pragma unroll
        for (int kk = 0; kk < 32; ++kk) {
            float w = w2s[(k0 + kk) * 32 + c];
#pragma unroll
            for (int r = 0; r < 8; ++r)
                acc[r] += hs[(rg + 8 * r) * 32 + kk] * w;
        }
    }
#pragma unroll
    for (int r = 0; r < 8; ++r) {
        int rw = rowbase + rg + 8 * r;
        if (rw < NV) g_qs[(size_t)rw * 32 + c] = acc[r];
    }
}

// ---------------- out: mean_j q[j] + s + b' --------------------------------
__global__ __launch_bounds__(256) void k_out(float* __restrict__ out)
{
    int t = threadIdx.x;
    int slot = t >> 4;
    int c = t & 15;
    int i = blockIdx.x * 16 + slot;
    if (i >= NV) return;
    int beg = g_off[i], end = g_off[i + 1];
    float acc = 0.f;
    for (int e = beg; e < end; ++e) {
        int s = g_srcs[e];
        acc += g_qs[(size_t)s * 32 + c];
    }
    int deg = end - beg;
    float inv = 1.0f / (float)(deg > 0 ? deg : 1);
    out[(size_t)i * 16 + c] = acc * inv + g_qs[(size_t)i * 32 + 16 + c] + g_bp[c];
}

// ---------------- launch ----------------------------------------------------
extern "C" void kernel_launch(void* const* d_in, const int* in_sizes, int n_in,
                              void* d_out, int out_size)
{
    const float* x   = (const float*)d_in[0];
    const int*   ei  = (const int*)d_in[1];   // int32 [2,E]
    const float* W1l = (const float*)d_in[2];
    const float* b1  = (const float*)d_in[3];
    const float* W1r = (const float*)d_in[4];
    const float* W2l = (const float*)d_in[5];
    const float* b2  = (const float*)d_in[6];
    const float* W2r = (const float*)d_in[7];
    const float* Wc  = (const float*)d_in[8];
    const float* bc  = (const float*)d_in[9];
    float* out = (float*)d_out;

    // prep (launches 1-5), then gemm1 as launch 6 (ncu -s 5 -c 1 target)
    k_split<<<(NV * 256) / 256, 256>>>(x);
    k_prepwT<<<(512 * 256) / 256, 256>>>(W1l, W1r);
    k_prepw2<<<(256 * 32) / 256, 256>>>(W2l, W2r, Wc);
    k_prepb<<<1, 16>>>(b2, Wc, bc);
    k_zero<<<(NV + 255) / 256, 256>>>();

    k_gemm1_wmma<<<dim3(8, 157), 256>>>();

    // CSR build (independent of gemm1)
    k_hist<<<(EN + 255) / 256, 256>>>(ei);
    k_scan<<<1, 1024>>>();
    k_scatter<<<(EN + 255) / 256, 256>>>(ei);

    // layer 1 aggregation
    k_agg1<<<NV, 256>>>(b1);

    // layer 2 (folded with classifier)
    k_gemm2<<<(NV + 63) / 64, 256>>>();
    k_out<<<(NV + 15) / 16, 256>>>(out);
}

// round 9
// speedup vs baseline: 1.2904x; 1.1755x over previous
#include <cuda_runtime.h>
#include <cuda_bf16.h>
#include <mma.h>
#include <cstdint>

using namespace nvcuda;

#define NV  20000
#define NVP 20096            // padded rows (multiple of 128) for unmasked wmma ld/st
#define EN  640000

// ---------------- scratch (device globals; no allocation allowed) ----------
__device__ int   g_deg[NV];
__device__ int   g_off[NV + 1];
__device__ int   g_cur[NV];
__device__ int   g_srcs[EN];
__device__ float g_w2[256 * 32];     // [K=256][N=32] = [W2l@Wc | W2r@Wc]
__device__ float g_bp[16];           // b2@Wc + bc
__device__ __nv_bfloat16 g_y[NVP * 256];   // x @ W1l  (bf16, padded)
__device__ float g_r[NVP * 256];     // x @ W1r   (padded)
__device__ float g_h[NV * 256];      // relu(mean(y) + r + b1)
__device__ float g_qs[NV * 32];      // [h@W2lWc | h@W2rWc]

__device__ __nv_bfloat16 g_xh[NVP * 256];    // bf16 hi of x (pad rows are zero-init)
__device__ __nv_bfloat16 g_xl[NVP * 256];    // bf16 lo of x
__device__ __nv_bfloat16 g_whT[512 * 256];   // [N=512][K=256] bf16 hi of [W1l|W1r]
__device__ __nv_bfloat16 g_wlT[512 * 256];   // bf16 lo

// ---------------- split x (+ zero g_deg, saves a launch) --------------------
__global__ void k_split(const float* __restrict__ x)
{
    int i = blockIdx.x * blockDim.x + threadIdx.x;
    if (i < NV * 256) {
        float v = x[i];
        __nv_bfloat16 h = __float2bfloat16(v);
        g_xh[i] = h;
        g_xl[i] = __float2bfloat16(v - __bfloat162float(h));
    }
    if (i < NV) g_deg[i] = 0;
}

__global__ void k_prepwT(const float* __restrict__ W1l, const float* __restrict__ W1r)
{
    int i = blockIdx.x * blockDim.x + threadIdx.x;   // 512*256
    if (i < 512 * 256) {
        int n = i >> 8, k = i & 255;
        float w = (n < 256) ? W1l[k * 256 + n] : W1r[k * 256 + (n - 256)];
        __nv_bfloat16 h = __float2bfloat16(w);
        g_whT[i] = h;
        g_wlT[i] = __float2bfloat16(w - __bfloat162float(h));
    }
}

// warp-per-output: g_w2 (8192 dots) + g_bp (16 dots), shuffle-reduced
__global__ __launch_bounds__(256) void k_prepw2b(
    const float* __restrict__ W2l, const float* __restrict__ W2r,
    const float* __restrict__ Wc,  const float* __restrict__ b2,
    const float* __restrict__ bc)
{
    int w = (blockIdx.x * blockDim.x + threadIdx.x) >> 5;
    int lane = threadIdx.x & 31;
    if (w < 8192) {
        int k = w >> 5, n = w & 31;
        const float* W = (n < 16) ? W2l : W2r;
        int c = n & 15;
        float acc = 0.f;
#pragma unroll
        for (int m = lane; m < 256; m += 32)
            acc += W[k * 256 + m] * Wc[m * 16 + c];
#pragma unroll
        for (int o = 16; o; o >>= 1) acc += __shfl_xor_sync(~0u, acc, o);
        if (lane == 0) g_w2[k * 32 + n] = acc;
    } else if (w < 8192 + 16) {
        int c = w - 8192;
        float acc = 0.f;
#pragma unroll
        for (int m = lane; m < 256; m += 32)
            acc += b2[m] * Wc[m * 16 + c];
#pragma unroll
        for (int o = 16; o; o >>= 1) acc += __shfl_xor_sync(~0u, acc, o);
        if (lane == 0) g_bp[c] = bc[c] + acc;
    }
}

// ---------------- CSR build ------------------------------------------------
__global__ void k_hist(const int* __restrict__ ei)
{
    int e = blockIdx.x * blockDim.x + threadIdx.x;
    if (e < EN) {
        unsigned dst = (unsigned)ei[EN + e];
        if (dst < NV) atomicAdd(&g_deg[dst], 1);
    }
}

__global__ void k_scan()
{
    __shared__ int part[1024];
    const int CH = 20;
    int t = threadIdx.x;
    int base = t * CH;
    int s = 0;
#pragma unroll
    for (int j = 0; j < CH; ++j) {
        int idx = base + j;
        if (idx < NV) s += g_deg[idx];
    }
    part[t] = s;
    __syncthreads();
    for (int off = 1; off < 1024; off <<= 1) {
        int v = 0;
        if (t >= off) v = part[t - off];
        __syncthreads();
        if (t >= off) part[t] += v;
        __syncthreads();
    }
    int run = (t == 0) ? 0 : part[t - 1];
#pragma unroll
    for (int j = 0; j < CH; ++j) {
        int idx = base + j;
        if (idx < NV) {
            g_off[idx] = run;
            g_cur[idx] = run;
            run += g_deg[idx];
        }
    }
    if (t == 0) g_off[NV] = EN;
}

__global__ void k_scatter(const int* __restrict__ ei)
{
    int e = blockIdx.x * blockDim.x + threadIdx.x;
    if (e < EN) {
        unsigned src = (unsigned)ei[e];
        unsigned dst = (unsigned)ei[EN + e];
        if (dst < NV && src < NV) {
            int pos = atomicAdd(&g_cur[dst], 1);
            g_srcs[pos] = (int)src;
        }
    }
}

// ---------------- wmma GEMM1: [y|r] = x @ [W1l|W1r] -------------------------
// Split bf16: y = xh@wh + xl@wh + xh@wl, fp32 accum (HMMA).
// B staged twice (wh reused for the xh and xl passes).
// y stored bf16 (SMEM bounce); r stored fp32 direct.
#define LDB 264
__global__ __launch_bounds__(256) void k_gemm1_wmma()
{
    __shared__ __align__(16) char smraw[64 * LDB * 2];   // 33792 B
    __nv_bfloat16* bs = (__nv_bfloat16*)smraw;
    float* stg = (float*)smraw;

    int tid = threadIdx.x;
    int wid = tid >> 5;
    int lane = tid & 31;
    int bx = blockIdx.x;                     // N tile 0..7
    int by = blockIdx.y;                     // M tile 0..156
    int nbase = bx * 64;
    int row = by * 128 + wid * 16;

    wmma::fragment<wmma::accumulator, 16, 16, 16, float> acc[4];
#pragma unroll
    for (int j = 0; j < 4; ++j) wmma::fill_fragment(acc[j], 0.0f);

    wmma::fragment<wmma::matrix_a, 16, 16, 16, __nv_bfloat16, wmma::row_major> af;
    wmma::fragment<wmma::matrix_b, 16, 16, 16, __nv_bfloat16, wmma::col_major> bf;

    // ---- stage wh tile ----
    for (int i = tid; i < 64 * 32; i += 256) {
        int r = i >> 5, c = i & 31;
        *(uint4*)&bs[r * LDB + c * 8] =
            *(const uint4*)&g_whT[(size_t)(nbase + r) * 256 + c * 8];
    }
    __syncthreads();

    // pass 1: xh @ wh
#pragma unroll 4
    for (int k0 = 0; k0 < 256; k0 += 16) {
        wmma::load_matrix_sync(af, g_xh + (size_t)row * 256 + k0, 256);
#pragma unroll
        for (int j = 0; j < 4; ++j) {
            wmma::load_matrix_sync(bf, bs + (j * 16) * LDB + k0, LDB);
            wmma::mma_sync(acc[j], af, bf, acc[j]);
        }
    }
    // pass 2: xl @ wh
#pragma unroll 4
    for (int k0 = 0; k0 < 256; k0 += 16) {
        wmma::load_matrix_sync(af, g_xl + (size_t)row * 256 + k0, 256);
#pragma unroll
        for (int j = 0; j < 4; ++j) {
            wmma::load_matrix_sync(bf, bs + (j * 16) * LDB + k0, LDB);
            wmma::mma_sync(acc[j], af, bf, acc[j]);
        }
    }
    __syncthreads();

    // ---- stage wl tile ----
    for (int i = tid; i < 64 * 32; i += 256) {
        int r = i >> 5, c = i & 31;
        *(uint4*)&bs[r * LDB + c * 8] =
            *(const uint4*)&g_wlT[(size_t)(nbase + r) * 256 + c * 8];
    }
    __syncthreads();

    // pass 3: xh @ wl
#pragma unroll 4
    for (int k0 = 0; k0 < 256; k0 += 16) {
        wmma::load_matrix_sync(af, g_xh + (size_t)row * 256 + k0, 256);
#pragma unroll
        for (int j = 0; j < 4; ++j) {
            wmma::load_matrix_sync(bf, bs + (j * 16) * LDB + k0, LDB);
            wmma::mma_sync(acc[j], af, bf, acc[j]);
        }
    }
    __syncthreads();   // done reading bs; smem reused as fp32 staging

    if (bx < 4) {
        // y path: bounce through smem, convert to bf16, coalesced store
        float* w = stg + wid * (16 * 64);
#pragma unroll
        for (int j = 0; j < 4; ++j)
            wmma::store_matrix_sync(w + j * 16, acc[j], 64, wmma::mem_row_major);
        __syncwarp();
#pragma unroll
        for (int rr = 0; rr < 16; ++rr) {
            float f0 = w[rr * 64 + 2 * lane];
            float f1 = w[rr * 64 + 2 * lane + 1];
            __nv_bfloat162 p = __floats2bfloat162_rn(f0, f1);
            *(__nv_bfloat162*)&g_y[(size_t)(row + rr) * 256 + nbase + 2 * lane] = p;
        }
    } else {
        float* dstbase = g_r + (size_t)row * 256 + (nbase - 256);
#pragma unroll
        for (int j = 0; j < 4; ++j)
            wmma::store_matrix_sync(dstbase + j * 16, acc[j], 256, wmma::mem_row_major);
    }
}

// ---------------- agg1 + relu: h = relu(mean_j y[j] + r + b1) ---------------
// 128 threads/vertex, bf16x2 gathers (halved traffic vs fp32)
__global__ __launch_bounds__(128) void k_agg1(const float* __restrict__ b1)
{
    int i = blockIdx.x;
    int t = threadIdx.x;
    int beg = g_off[i], end = g_off[i + 1];

    float s0x = 0.f, s0y = 0.f, s1x = 0.f, s1y = 0.f;
    float s2x = 0.f, s2y = 0.f, s3x = 0.f, s3y = 0.f;
    int e = beg;
    for (; e + 4 <= end; e += 4) {
        int a = g_srcs[e + 0], b = g_srcs[e + 1];
        int c = g_srcs[e + 2], d = g_srcs[e + 3];
        float2 v0 = __bfloat1622float2(*(const __nv_bfloat162*)&g_y[(size_t)a * 256 + 2 * t]);
        float2 v1 = __bfloat1622float2(*(const __nv_bfloat162*)&g_y[(size_t)b * 256 + 2 * t]);
        float2 v2 = __bfloat1622float2(*(const __nv_bfloat162*)&g_y[(size_t)c * 256 + 2 * t]);
        float2 v3 = __bfloat1622float2(*(const __nv_bfloat162*)&g_y[(size_t)d * 256 + 2 * t]);
        s0x += v0.x; s0y += v0.y;
        s1x += v1.x; s1y += v1.y;
        s2x += v2.x; s2y += v2.y;
        s3x += v3.x; s3y += v3.y;
    }
    for (; e < end; ++e) {
        float2 v = __bfloat1622float2(*(const __nv_bfloat162*)&g_y[(size_t)g_srcs[e] * 256 + 2 * t]);
        s0x += v.x; s0y += v.y;
    }

    float sx = (s0x + s1x) + (s2x + s3x);
    float sy = (s0y + s1y) + (s2y + s3y);
    int deg = end - beg;
    float inv = 1.0f / (float)(deg > 0 ? deg : 1);
    float2 rr = *(const float2*)&g_r[(size_t)i * 256 + 2 * t];
    float2 bb = *(const float2*)&b1[2 * t];
    float v0 = sx * inv + rr.x + bb.x;
    float v1 = sy * inv + rr.y + bb.y;
    g_h[(size_t)i * 256 + 2 * t]     = v0 > 0.f ? v0 : 0.f;
    g_h[(size_t)i * 256 + 2 * t + 1] = v1 > 0.f ? v1 : 0.f;
}

// ---------------- GEMM2: g_qs = h @ g_w2  (M=20000, N=32, K=256) ------------
__global__ __launch_bounds__(256) void k_gemm2()
{
    __shared__ float w2s[256 * 32];
    __shared__ float hs[64 * 32];
    int t = threadIdx.x;
    for (int i = t; i < 256 * 32; i += 256) w2s[i] = g_w2[i];

    int rowbase = blockIdx.x * 64;
    int c = t & 31, rg = t >> 5;
    float acc[8];
#pragma unroll
    for (int r = 0; r < 8; ++r) acc[r] = 0.f;

    for (int k0 = 0; k0 < 256; k0 += 32) {
        __syncthreads();
        for (int i = t; i < 64 * 32; i += 256) {
            int rr = i >> 5, kk = i & 31;
            int rw = rowbase + rr;
            if (rw >= NV) rw = NV - 1;
            hs[i] = g_h[(size_t)rw * 256 + k0 + kk];
        }
        __syncthreads();
#pragma unroll
        for (int kk = 0; kk < 32; ++kk) {
            float w = w2s[(k0 + kk) * 32 + c];
#pragma unroll
            for (int r = 0; r < 8; ++r)
                acc[r] += hs[(rg + 8 * r) * 32 + kk] * w;
        }
    }
#pragma unroll
    for (int r = 0; r < 8; ++r) {
        int rw = rowbase + rg + 8 * r;
        if (rw < NV) g_qs[(size_t)rw * 32 + c] = acc[r];
    }
}

// ---------------- out: mean_j q[j] + s + b' --------------------------------
__global__ __launch_bounds__(256) void k_out(float* __restrict__ out)
{
    int t = threadIdx.x;
    int slot = t >> 4;
    int c = t & 15;
    int i = blockIdx.x * 16 + slot;
    if (i >= NV) return;
    int beg = g_off[i], end = g_off[i + 1];
    float acc = 0.f;
    for (int e = beg; e < end; ++e) {
        int s = g_srcs[e];
        acc += g_qs[(size_t)s * 32 + c];
    }
    int deg = end - beg;
    float inv = 1.0f / (float)(deg > 0 ? deg : 1);
    out[(size_t)i * 16 + c] = acc * inv + g_qs[(size_t)i * 32 + 16 + c] + g_bp[c];
}

// ---------------- launch ----------------------------------------------------
extern "C" void kernel_launch(void* const* d_in, const int* in_sizes, int n_in,
                              void* d_out, int out_size)
{
    const float* x   = (const float*)d_in[0];
    const int*   ei  = (const int*)d_in[1];   // int32 [2,E]
    const float* W1l = (const float*)d_in[2];
    const float* b1  = (const float*)d_in[3];
    const float* W1r = (const float*)d_in[4];
    const float* W2l = (const float*)d_in[5];
    const float* b2  = (const float*)d_in[6];
    const float* W2r = (const float*)d_in[7];
    const float* Wc  = (const float*)d_in[8];
    const float* bc  = (const float*)d_in[9];
    float* out = (float*)d_out;

    k_split<<<(NV * 256) / 256, 256>>>(x);                 // 1 (also zeros g_deg)
    k_prepwT<<<(512 * 256) / 256, 256>>>(W1l, W1r);        // 2
    k_prepw2b<<<1026, 256>>>(W2l, W2r, Wc, b2, bc);        // 3

    k_gemm1_wmma<<<dim3(8, 157), 256>>>();                 // 4 (ncu target)

    k_hist<<<(EN + 255) / 256, 256>>>(ei);                 // 5
    k_scan<<<1, 1024>>>();                                 // 6
    k_scatter<<<(EN + 255) / 256, 256>>>(ei);              // 7

    k_agg1<<<NV, 128>>>(b1);                               // 8

    k_gemm2<<<(NV + 63) / 64, 256>>>();                    // 9
    k_out<<<(NV + 15) / 16, 256>>>(out);                   // 10
}

// round 10
// speedup vs baseline: 1.3962x; 1.0820x over previous
#include <cuda_runtime.h>
#include <cuda_bf16.h>
#include <mma.h>
#include <cstdint>

using namespace nvcuda;

#define NV  20000
#define NVP 20224            // padded rows (multiple of 256) for unmasked wmma ld/st
#define EN  640000

// ---------------- scratch (device globals; no allocation allowed) ----------
__device__ int   g_deg[NV];
__device__ int   g_off[NV + 1];
__device__ int   g_cur[NV];
__device__ int   g_srcs[EN];
__device__ float g_w2[256 * 32];     // [K=256][N=32] = [W2l@Wc | W2r@Wc]
__device__ float g_bp[16];           // b2@Wc + bc
__device__ __nv_bfloat16 g_y[NVP * 256];   // x @ W1l  (bf16, padded)
__device__ float g_r[NVP * 256];     // x @ W1r   (padded)
__device__ float g_h[NV * 256];      // relu(mean(y) + r + b1)
__device__ float g_qs[NV * 32];      // [h@W2lWc | h@W2rWc]

__device__ __nv_bfloat16 g_xh[NVP * 256];    // bf16 hi of x (pad rows stay zero)
__device__ __nv_bfloat16 g_xl[NVP * 256];    // bf16 lo of x
__device__ __nv_bfloat16 g_whT[512 * 256];   // [N=512][K=256] bf16 hi of [W1l|W1r]
__device__ __nv_bfloat16 g_wlT[512 * 256];   // bf16 lo

// ---------------- merged prologue: split + prepwT + prepw2b + hist ----------
// block ranges:
//   [0, 20000)        : split x into xh/xl (+ zero g_deg)
//   [20000, 20512)    : split/transpose W1 into whT/wlT
//   [20512, 21538)    : W2@Wc, b2@Wc+bc (warp-per-output)
//   [21538, 24038)    : degree histogram
__global__ __launch_bounds__(256) void k_prologue(
    const float* __restrict__ x,
    const float* __restrict__ W1l, const float* __restrict__ W1r,
    const float* __restrict__ W2l, const float* __restrict__ W2r,
    const float* __restrict__ Wc,  const float* __restrict__ b2,
    const float* __restrict__ bc,  const int* __restrict__ ei)
{
    int b = blockIdx.x;
    int t = threadIdx.x;

    if (b < 20000) {
        int i = b * 256 + t;
        float v = x[i];
        __nv_bfloat16 h = __float2bfloat16(v);
        g_xh[i] = h;
        g_xl[i] = __float2bfloat16(v - __bfloat162float(h));
        if (i < NV) g_deg[i] = 0;
    } else if (b < 20512) {
        int i = (b - 20000) * 256 + t;     // 512*256
        int n = i >> 8, k = i & 255;
        float w = (n < 256) ? W1l[k * 256 + n] : W1r[k * 256 + (n - 256)];
        __nv_bfloat16 h = __float2bfloat16(w);
        g_whT[i] = h;
        g_wlT[i] = __float2bfloat16(w - __bfloat162float(h));
    } else if (b < 21538) {
        int w = ((b - 20512) * 256 + t) >> 5;
        int lane = t & 31;
        if (w < 8192) {
            int k = w >> 5, n = w & 31;
            const float* W = (n < 16) ? W2l : W2r;
            int c = n & 15;
            float acc = 0.f;
#pragma unroll
            for (int m = lane; m < 256; m += 32)
                acc += W[k * 256 + m] * Wc[m * 16 + c];
#pragma unroll
            for (int o = 16; o; o >>= 1) acc += __shfl_xor_sync(~0u, acc, o);
            if (lane == 0) g_w2[k * 32 + n] = acc;
        } else if (w < 8192 + 16) {
            int c = w - 8192;
            float acc = 0.f;
#pragma unroll
            for (int m = lane; m < 256; m += 32)
                acc += b2[m] * Wc[m * 16 + c];
#pragma unroll
            for (int o = 16; o; o >>= 1) acc += __shfl_xor_sync(~0u, acc, o);
            if (lane == 0) g_bp[c] = bc[c] + acc;
        }
    } else {
        int e = (b - 21538) * 256 + t;
        if (e < EN) {
            unsigned dst = (unsigned)ei[EN + e];
            if (dst < NV) atomicAdd(&g_deg[dst], 1);
        }
    }
}

// ---------------- CSR scan + scatter ---------------------------------------
__global__ void k_scan()
{
    __shared__ int part[1024];
    const int CH = 20;
    int t = threadIdx.x;
    int base = t * CH;
    int s = 0;
#pragma unroll
    for (int j = 0; j < CH; ++j) {
        int idx = base + j;
        if (idx < NV) s += g_deg[idx];
    }
    part[t] = s;
    __syncthreads();
    for (int off = 1; off < 1024; off <<= 1) {
        int v = 0;
        if (t >= off) v = part[t - off];
        __syncthreads();
        if (t >= off) part[t] += v;
        __syncthreads();
    }
    int run = (t == 0) ? 0 : part[t - 1];
#pragma unroll
    for (int j = 0; j < CH; ++j) {
        int idx = base + j;
        if (idx < NV) {
            g_off[idx] = run;
            g_cur[idx] = run;
            run += g_deg[idx];
        }
    }
    if (t == 0) g_off[NV] = EN;
}

__global__ void k_scatter(const int* __restrict__ ei)
{
    int e = blockIdx.x * blockDim.x + threadIdx.x;
    if (e < EN) {
        unsigned src = (unsigned)ei[e];
        unsigned dst = (unsigned)ei[EN + e];
        if (dst < NV && src < NV) {
            int pos = atomicAdd(&g_cur[dst], 1);
            g_srcs[pos] = (int)src;
        }
    }
}

// ---------------- wmma GEMM1: [y|r] = x @ [W1l|W1r] -------------------------
// Split bf16: y = xh@wh + xl@wh + xh@wl, fp32 accum (HMMA).
// CTA: M=256 x N=64, 8 warps, warp tile 32x64 (B frag reused across 2 M-frags).
#define LDB 264
__global__ __launch_bounds__(256) void k_gemm1_wmma()
{
    __shared__ __align__(16) char smraw[64 * LDB * 2];   // 33792 B
    __nv_bfloat16* bs = (__nv_bfloat16*)smraw;
    float* stg = (float*)smraw;

    int tid = threadIdx.x;
    int wid = tid >> 5;
    int lane = tid & 31;
    int bx = blockIdx.x;                     // N tile 0..7
    int by = blockIdx.y;                     // M tile 0..78
    int nbase = bx * 64;
    int row = by * 256 + wid * 32;

    wmma::fragment<wmma::accumulator, 16, 16, 16, float> acc[2][4];
#pragma unroll
    for (int i = 0; i < 2; ++i)
#pragma unroll
        for (int j = 0; j < 4; ++j) wmma::fill_fragment(acc[i][j], 0.0f);

    wmma::fragment<wmma::matrix_a, 16, 16, 16, __nv_bfloat16, wmma::row_major> af0, af1;
    wmma::fragment<wmma::matrix_b, 16, 16, 16, __nv_bfloat16, wmma::col_major> bf;

    // ---- stage wh tile ----
    for (int i = tid; i < 64 * 32; i += 256) {
        int r = i >> 5, c = i & 31;
        *(uint4*)&bs[r * LDB + c * 8] =
            *(const uint4*)&g_whT[(size_t)(nbase + r) * 256 + c * 8];
    }
    __syncthreads();

    // pass 1: xh @ wh
#pragma unroll 2
    for (int k0 = 0; k0 < 256; k0 += 16) {
        wmma::load_matrix_sync(af0, g_xh + (size_t)row * 256 + k0, 256);
        wmma::load_matrix_sync(af1, g_xh + (size_t)(row + 16) * 256 + k0, 256);
#pragma unroll
        for (int j = 0; j < 4; ++j) {
            wmma::load_matrix_sync(bf, bs + (j * 16) * LDB + k0, LDB);
            wmma::mma_sync(acc[0][j], af0, bf, acc[0][j]);
            wmma::mma_sync(acc[1][j], af1, bf, acc[1][j]);
        }
    }
    // pass 2: xl @ wh
#pragma unroll 2
    for (int k0 = 0; k0 < 256; k0 += 16) {
        wmma::load_matrix_sync(af0, g_xl + (size_t)row * 256 + k0, 256);
        wmma::load_matrix_sync(af1, g_xl + (size_t)(row + 16) * 256 + k0, 256);
#pragma unroll
        for (int j = 0; j < 4; ++j) {
            wmma::load_matrix_sync(bf, bs + (j * 16) * LDB + k0, LDB);
            wmma::mma_sync(acc[0][j], af0, bf, acc[0][j]);
            wmma::mma_sync(acc[1][j], af1, bf, acc[1][j]);
        }
    }
    __syncthreads();

    // ---- stage wl tile ----
    for (int i = tid; i < 64 * 32; i += 256) {
        int r = i >> 5, c = i & 31;
        *(uint4*)&bs[r * LDB + c * 8] =
            *(const uint4*)&g_wlT[(size_t)(nbase + r) * 256 + c * 8];
    }
    __syncthreads();

    // pass 3: xh @ wl
#pragma unroll 2
    for (int k0 = 0; k0 < 256; k0 += 16) {
        wmma::load_matrix_sync(af0, g_xh + (size_t)row * 256 + k0, 256);
        wmma::load_matrix_sync(af1, g_xh + (size_t)(row + 16) * 256 + k0, 256);
#pragma unroll
        for (int j = 0; j < 4; ++j) {
            wmma::load_matrix_sync(bf, bs + (j * 16) * LDB + k0, LDB);
            wmma::mma_sync(acc[0][j], af0, bf, acc[0][j]);
            wmma::mma_sync(acc[1][j], af1, bf, acc[1][j]);
        }
    }
    __syncthreads();   // done reading bs; smem reused as fp32 staging

    if (bx < 4) {
        // y path: per-warp smem bounce (16x64 fp32 = 4KB), convert to bf16
        float* w = stg + wid * (16 * 64);
#pragma unroll
        for (int i = 0; i < 2; ++i) {
#pragma unroll
            for (int j = 0; j < 4; ++j)
                wmma::store_matrix_sync(w + j * 16, acc[i][j], 64, wmma::mem_row_major);
            __syncwarp();
#pragma unroll
            for (int rr = 0; rr < 16; ++rr) {
                float f0 = w[rr * 64 + 2 * lane];
                float f1 = w[rr * 64 + 2 * lane + 1];
                __nv_bfloat162 p = __floats2bfloat162_rn(f0, f1);
                *(__nv_bfloat162*)&g_y[(size_t)(row + i * 16 + rr) * 256 + nbase + 2 * lane] = p;
            }
            __syncwarp();
        }
    } else {
        float* dstbase = g_r + (size_t)row * 256 + (nbase - 256);
#pragma unroll
        for (int i = 0; i < 2; ++i)
#pragma unroll
            for (int j = 0; j < 4; ++j)
                wmma::store_matrix_sync(dstbase + (size_t)i * 16 * 256 + j * 16,
                                        acc[i][j], 256, wmma::mem_row_major);
    }
}

// ---------------- agg1 + relu: h = relu(mean_j y[j] + r + b1) ---------------
__global__ __launch_bounds__(128) void k_agg1(const float* __restrict__ b1)
{
    int i = blockIdx.x;
    int t = threadIdx.x;
    int beg = g_off[i], end = g_off[i + 1];

    float s0x = 0.f, s0y = 0.f, s1x = 0.f, s1y = 0.f;
    float s2x = 0.f, s2y = 0.f, s3x = 0.f, s3y = 0.f;
    int e = beg;
    for (; e + 4 <= end; e += 4) {
        int a = g_srcs[e + 0], b = g_srcs[e + 1];
        int c = g_srcs[e + 2], d = g_srcs[e + 3];
        float2 v0 = __bfloat1622float2(*(const __nv_bfloat162*)&g_y[(size_t)a * 256 + 2 * t]);
        float2 v1 = __bfloat1622float2(*(const __nv_bfloat162*)&g_y[(size_t)b * 256 + 2 * t]);
        float2 v2 = __bfloat1622float2(*(const __nv_bfloat162*)&g_y[(size_t)c * 256 + 2 * t]);
        float2 v3 = __bfloat1622float2(*(const __nv_bfloat162*)&g_y[(size_t)d * 256 + 2 * t]);
        s0x += v0.x; s0y += v0.y;
        s1x += v1.x; s1y += v1.y;
        s2x += v2.x; s2y += v2.y;
        s3x += v3.x; s3y += v3.y;
    }
    for (; e < end; ++e) {
        float2 v = __bfloat1622float2(*(const __nv_bfloat162*)&g_y[(size_t)g_srcs[e] * 256 + 2 * t]);
        s0x += v.x; s0y += v.y;
    }

    float sx = (s0x + s1x) + (s2x + s3x);
    float sy = (s0y + s1y) + (s2y + s3y);
    int deg = end - beg;
    float inv = 1.0f / (float)(deg > 0 ? deg : 1);
    float2 rr = *(const float2*)&g_r[(size_t)i * 256 + 2 * t];
    float2 bb = *(const float2*)&b1[2 * t];
    float v0 = sx * inv + rr.x + bb.x;
    float v1 = sy * inv + rr.y + bb.y;
    g_h[(size_t)i * 256 + 2 * t]     = v0 > 0.f ? v0 : 0.f;
    g_h[(size_t)i * 256 + 2 * t + 1] = v1 > 0.f ? v1 : 0.f;
}

// ---------------- GEMM2: g_qs = h @ g_w2  (M=20000, N=32, K=256) ------------
__global__ __launch_bounds__(256) void k_gemm2()
{
    __shared__ float w2s[256 * 32];
    __shared__ float hs[64 * 32];
    int t = threadIdx.x;
    for (int i = t; i < 256 * 32; i += 256) w2s[i] = g_w2[i];

    int rowbase = blockIdx.x * 64;
    int c = t & 31, rg = t >> 5;
    float acc[8];
#pragma unroll
    for (int r = 0; r < 8; ++r) acc[r] = 0.f;

    for (int k0 = 0; k0 < 256; k0 += 32) {
        __syncthreads();
        for (int i = t; i < 64 * 32; i += 256) {
            int rr = i >> 5, kk = i & 31;
            int rw = rowbase + rr;
            if (rw >= NV) rw = NV - 1;
            hs[i] = g_h[(size_t)rw * 256 + k0 + kk];
        }
        __syncthreads();
#pragma unroll
        for (int kk = 0; kk < 32; ++kk) {
            float w = w2s[(k0 + kk) * 32 + c];
#pragma unroll
            for (int r = 0; r < 8; ++r)
                acc[r] += hs[(rg + 8 * r) * 32 + kk] * w;
        }
    }
#pragma unroll
    for (int r = 0; r < 8; ++r) {
        int rw = rowbase + rg + 8 * r;
        if (rw < NV) g_qs[(size_t)rw * 32 + c] = acc[r];
    }
}

// ---------------- out: mean_j q[j] + s + b' --------------------------------
__global__ __launch_bounds__(256) void k_out(float* __restrict__ out)
{
    int t = threadIdx.x;
    int slot = t >> 4;
    int c = t & 15;
    int i = blockIdx.x * 16 + slot;
    if (i >= NV) return;
    int beg = g_off[i], end = g_off[i + 1];
    float acc = 0.f;
    for (int e = beg; e < end; ++e) {
        int s = g_srcs[e];
        acc += g_qs[(size_t)s * 32 + c];
    }
    int deg = end - beg;
    float inv = 1.0f / (float)(deg > 0 ? deg : 1);
    out[(size_t)i * 16 + c] = acc * inv + g_qs[(size_t)i * 32 + 16 + c] + g_bp[c];
}

// ---------------- launch ----------------------------------------------------
extern "C" void kernel_launch(void* const* d_in, const int* in_sizes, int n_in,
                              void* d_out, int out_size)
{
    const float* x   = (const float*)d_in[0];
    const int*   ei  = (const int*)d_in[1];   // int32 [2,E]
    const float* W1l = (const float*)d_in[2];
    const float* b1  = (const float*)d_in[3];
    const float* W1r = (const float*)d_in[4];
    const float* W2l = (const float*)d_in[5];
    const float* b2  = (const float*)d_in[6];
    const float* W2r = (const float*)d_in[7];
    const float* Wc  = (const float*)d_in[8];
    const float* bc  = (const float*)d_in[9];
    float* out = (float*)d_out;

    k_prologue<<<24038, 256>>>(x, W1l, W1r, W2l, W2r, Wc, b2, bc, ei);  // 1
    k_gemm1_wmma<<<dim3(8, 79), 256>>>();                               // 2
    k_scan<<<1, 1024>>>();                                              // 3
    k_scatter<<<(EN + 255) / 256, 256>>>(ei);                           // 4
    k_agg1<<<NV, 128>>>(b1);                                            // 5
    k_gemm2<<<(NV + 63) / 64, 256>>>();                                 // 6
    k_out<<<(NV + 15) / 16, 256>>>(out);                                // 7
}

// round 11
// speedup vs baseline: 1.4722x; 1.0544x over previous
#include <cuda_runtime.h>
#include <cuda_bf16.h>
#include <mma.h>
#include <cstdint>

using namespace nvcuda;

#define NV  20000
#define NVP 20224            // padded rows (79 * 256) for unmasked wmma ld/st
#define EN  640000

// ---------------- scratch (device globals; no allocation allowed) ----------
__device__ int   g_deg[NV];
__device__ int   g_off[NV + 1];
__device__ int   g_cur[NV];
__device__ int   g_srcs[EN];
__device__ float g_w2[256 * 32];     // [K=256][N=32] = [W2l@Wc | W2r@Wc]
__device__ float g_bp[16];           // b2@Wc + bc
__device__ __nv_bfloat16 g_y[NVP * 256];   // x @ W1l  (bf16, padded)
__device__ float g_r[NVP * 256];     // x @ W1r   (padded)
__device__ float g_h[NV * 256];      // relu(mean(y) + r + b1)
__device__ float g_qs[NV * 32];      // [h@W2lWc | h@W2rWc]

__device__ __nv_bfloat16 g_xh[NVP * 256];    // bf16 hi of x (pad rows stay zero)
__device__ __nv_bfloat16 g_xl[NVP * 256];    // bf16 lo of x
__device__ __nv_bfloat16 g_whT[512 * 256];   // [N=512][K=256] bf16 hi of [W1l|W1r]
__device__ __nv_bfloat16 g_wlT[512 * 256];   // bf16 lo

// ---------------- merged prologue: split + prepwT + prepw2b + hist ----------
__global__ __launch_bounds__(256) void k_prologue(
    const float* __restrict__ x,
    const float* __restrict__ W1l, const float* __restrict__ W1r,
    const float* __restrict__ W2l, const float* __restrict__ W2r,
    const float* __restrict__ Wc,  const float* __restrict__ b2,
    const float* __restrict__ bc,  const int* __restrict__ ei)
{
    int b = blockIdx.x;
    int t = threadIdx.x;

    if (b < 20000) {
        int i = b * 256 + t;
        float v = x[i];
        __nv_bfloat16 h = __float2bfloat16(v);
        g_xh[i] = h;
        g_xl[i] = __float2bfloat16(v - __bfloat162float(h));
        if (i < NV) g_deg[i] = 0;
    } else if (b < 20512) {
        int i = (b - 20000) * 256 + t;     // 512*256
        int n = i >> 8, k = i & 255;
        float w = (n < 256) ? W1l[k * 256 + n] : W1r[k * 256 + (n - 256)];
        __nv_bfloat16 h = __float2bfloat16(w);
        g_whT[i] = h;
        g_wlT[i] = __float2bfloat16(w - __bfloat162float(h));
    } else if (b < 21538) {
        int w = ((b - 20512) * 256 + t) >> 5;
        int lane = t & 31;
        if (w < 8192) {
            int k = w >> 5, n = w & 31;
            const float* W = (n < 16) ? W2l : W2r;
            int c = n & 15;
            float acc = 0.f;
#pragma unroll
            for (int m = lane; m < 256; m += 32)
                acc += W[k * 256 + m] * Wc[m * 16 + c];
#pragma unroll
            for (int o = 16; o; o >>= 1) acc += __shfl_xor_sync(~0u, acc, o);
            if (lane == 0) g_w2[k * 32 + n] = acc;
        } else if (w < 8192 + 16) {
            int c = w - 8192;
            float acc = 0.f;
#pragma unroll
            for (int m = lane; m < 256; m += 32)
                acc += b2[m] * Wc[m * 16 + c];
#pragma unroll
            for (int o = 16; o; o >>= 1) acc += __shfl_xor_sync(~0u, acc, o);
            if (lane == 0) g_bp[c] = bc[c] + acc;
        }
    } else {
        int e = (b - 21538) * 256 + t;
        if (e < EN) {
            unsigned dst = (unsigned)ei[EN + e];
            if (dst < NV) atomicAdd(&g_deg[dst], 1);
        }
    }
}

// ---------------- CSR scan ---------------------------------------------------
__global__ void k_scan()
{
    __shared__ int part[1024];
    const int CH = 20;
    int t = threadIdx.x;
    int base = t * CH;
    int s = 0;
#pragma unroll
    for (int j = 0; j < CH; ++j) {
        int idx = base + j;
        if (idx < NV) s += g_deg[idx];
    }
    part[t] = s;
    __syncthreads();
    for (int off = 1; off < 1024; off <<= 1) {
        int v = 0;
        if (t >= off) v = part[t - off];
        __syncthreads();
        if (t >= off) part[t] += v;
        __syncthreads();
    }
    int run = (t == 0) ? 0 : part[t - 1];
#pragma unroll
    for (int j = 0; j < CH; ++j) {
        int idx = base + j;
        if (idx < NV) {
            g_off[idx] = run;
            g_cur[idx] = run;
            run += g_deg[idx];
        }
    }
    if (t == 0) g_off[NV] = EN;
}

// ---------------- gemm1 (wmma, warp tile 64x64) + scatter (merged) ----------
// blocks [0, 632):     gemm1  (bx = b&7 in N, by = b>>3 in M; CTA 256x64)
// blocks [632, 5632):  CSR scatter (5000 blocks x 128 thr = 640000 edges)
#define LDB 264
__global__ __launch_bounds__(128) void k_gemm1_sc(const int* __restrict__ ei)
{
    __shared__ __align__(16) char smraw[64 * LDB * 2];   // 33792 B
    int t = threadIdx.x;
    int b = blockIdx.x;

    if (b >= 632) {
        // ---------------- scatter part ----------------
        int e = (b - 632) * 128 + t;
        unsigned src = (unsigned)ei[e];
        unsigned dst = (unsigned)ei[EN + e];
        if (dst < NV && src < NV) {
            int pos = atomicAdd(&g_cur[dst], 1);
            g_srcs[pos] = (int)src;
        }
        return;
    }

    // ---------------- gemm part ----------------
    __nv_bfloat16* bs = (__nv_bfloat16*)smraw;
    float* stg = (float*)smraw;

    int wid = t >> 5;
    int lane = t & 31;
    int bx = b & 7;                          // N tile 0..7
    int by = b >> 3;                         // M tile 0..78
    int nbase = bx * 64;
    int row = by * 256 + wid * 64;

    wmma::fragment<wmma::accumulator, 16, 16, 16, float> acc[4][4];
#pragma unroll
    for (int i = 0; i < 4; ++i)
#pragma unroll
        for (int j = 0; j < 4; ++j) wmma::fill_fragment(acc[i][j], 0.0f);

    wmma::fragment<wmma::matrix_a, 16, 16, 16, __nv_bfloat16, wmma::row_major> af[4];
    wmma::fragment<wmma::matrix_b, 16, 16, 16, __nv_bfloat16, wmma::col_major> bf;

    // ---- stage wh tile (64 rows x 256 cols bf16) ----
    for (int i = t; i < 64 * 32; i += 128) {
        int r = i >> 5, c = i & 31;
        *(uint4*)&bs[r * LDB + c * 8] =
            *(const uint4*)&g_whT[(size_t)(nbase + r) * 256 + c * 8];
    }
    __syncthreads();

    // pass 1: xh @ wh ; pass 2: xl @ wh
#pragma unroll 1
    for (int pass = 0; pass < 2; ++pass) {
        const __nv_bfloat16* Asrc = pass ? g_xl : g_xh;
#pragma unroll 1
        for (int k0 = 0; k0 < 256; k0 += 16) {
#pragma unroll
            for (int i = 0; i < 4; ++i)
                wmma::load_matrix_sync(af[i], Asrc + (size_t)(row + i * 16) * 256 + k0, 256);
#pragma unroll
            for (int j = 0; j < 4; ++j) {
                wmma::load_matrix_sync(bf, bs + (j * 16) * LDB + k0, LDB);
#pragma unroll
                for (int i = 0; i < 4; ++i)
                    wmma::mma_sync(acc[i][j], af[i], bf, acc[i][j]);
            }
        }
    }
    __syncthreads();

    // ---- stage wl tile ----
    for (int i = t; i < 64 * 32; i += 128) {
        int r = i >> 5, c = i & 31;
        *(uint4*)&bs[r * LDB + c * 8] =
            *(const uint4*)&g_wlT[(size_t)(nbase + r) * 256 + c * 8];
    }
    __syncthreads();

    // pass 3: xh @ wl
#pragma unroll 1
    for (int k0 = 0; k0 < 256; k0 += 16) {
#pragma unroll
        for (int i = 0; i < 4; ++i)
            wmma::load_matrix_sync(af[i], g_xh + (size_t)(row + i * 16) * 256 + k0, 256);
#pragma unroll
        for (int j = 0; j < 4; ++j) {
            wmma::load_matrix_sync(bf, bs + (j * 16) * LDB + k0, LDB);
#pragma unroll
            for (int i = 0; i < 4; ++i)
                wmma::mma_sync(acc[i][j], af[i], bf, acc[i][j]);
        }
    }
    __syncthreads();   // done reading bs; smem reused as fp32 staging

    if (bx < 4) {
        // y path: per-warp smem bounce (16x64 fp32 = 4KB/warp), convert to bf16
        float* w = stg + wid * (16 * 64);
#pragma unroll
        for (int i = 0; i < 4; ++i) {
#pragma unroll
            for (int j = 0; j < 4; ++j)
                wmma::store_matrix_sync(w + j * 16, acc[i][j], 64, wmma::mem_row_major);
            __syncwarp();
#pragma unroll
            for (int rr = 0; rr < 16; ++rr) {
                float f0 = w[rr * 64 + 2 * lane];
                float f1 = w[rr * 64 + 2 * lane + 1];
                __nv_bfloat162 p = __floats2bfloat162_rn(f0, f1);
                *(__nv_bfloat162*)&g_y[(size_t)(row + i * 16 + rr) * 256 + nbase + 2 * lane] = p;
            }
            __syncwarp();
        }
    } else {
        float* dstbase = g_r + (size_t)row * 256 + (nbase - 256);
#pragma unroll
        for (int i = 0; i < 4; ++i)
#pragma unroll
            for (int j = 0; j < 4; ++j)
                wmma::store_matrix_sync(dstbase + (size_t)i * 16 * 256 + j * 16,
                                        acc[i][j], 256, wmma::mem_row_major);
    }
}

// ---------------- agg1 + relu: h = relu(mean_j y[j] + r + b1) ---------------
__global__ __launch_bounds__(128) void k_agg1(const float* __restrict__ b1)
{
    int i = blockIdx.x;
    int t = threadIdx.x;
    int beg = g_off[i], end = g_off[i + 1];

    float s0x = 0.f, s0y = 0.f, s1x = 0.f, s1y = 0.f;
    float s2x = 0.f, s2y = 0.f, s3x = 0.f, s3y = 0.f;
    int e = beg;
    for (; e + 4 <= end; e += 4) {
        int a = g_srcs[e + 0], b = g_srcs[e + 1];
        int c = g_srcs[e + 2], d = g_srcs[e + 3];
        float2 v0 = __bfloat1622float2(*(const __nv_bfloat162*)&g_y[(size_t)a * 256 + 2 * t]);
        float2 v1 = __bfloat1622float2(*(const __nv_bfloat162*)&g_y[(size_t)b * 256 + 2 * t]);
        float2 v2 = __bfloat1622float2(*(const __nv_bfloat162*)&g_y[(size_t)c * 256 + 2 * t]);
        float2 v3 = __bfloat1622float2(*(const __nv_bfloat162*)&g_y[(size_t)d * 256 + 2 * t]);
        s0x += v0.x; s0y += v0.y;
        s1x += v1.x; s1y += v1.y;
        s2x += v2.x; s2y += v2.y;
        s3x += v3.x; s3y += v3.y;
    }
    for (; e < end; ++e) {
        float2 v = __bfloat1622float2(*(const __nv_bfloat162*)&g_y[(size_t)g_srcs[e] * 256 + 2 * t]);
        s0x += v.x; s0y += v.y;
    }

    float sx = (s0x + s1x) + (s2x + s3x);
    float sy = (s0y + s1y) + (s2y + s3y);
    int deg = end - beg;
    float inv = 1.0f / (float)(deg > 0 ? deg : 1);
    float2 rr = *(const float2*)&g_r[(size_t)i * 256 + 2 * t];
    float2 bb = *(const float2*)&b1[2 * t];
    float v0 = sx * inv + rr.x + bb.x;
    float v1 = sy * inv + rr.y + bb.y;
    g_h[(size_t)i * 256 + 2 * t]     = v0 > 0.f ? v0 : 0.f;
    g_h[(size_t)i * 256 + 2 * t + 1] = v1 > 0.f ? v1 : 0.f;
}

// ---------------- GEMM2: g_qs = h @ g_w2  (M=20000, N=32, K=256) ------------
__global__ __launch_bounds__(256) void k_gemm2()
{
    __shared__ float w2s[256 * 32];
    __shared__ float hs[64 * 32];
    int t = threadIdx.x;
    for (int i = t; i < 256 * 32; i += 256) w2s[i] = g_w2[i];

    int rowbase = blockIdx.x * 64;
    int c = t & 31, rg = t >> 5;
    float acc[8];
#pragma unroll
    for (int r = 0; r < 8; ++r) acc[r] = 0.f;

    for (int k0 = 0; k0 < 256; k0 += 32) {
        __syncthreads();
        for (int i = t; i < 64 * 32; i += 256) {
            int rr = i >> 5, kk = i & 31;
            int rw = rowbase + rr;
            if (rw >= NV) rw = NV - 1;
            hs[i] = g_h[(size_t)rw * 256 + k0 + kk];
        }
        __syncthreads();
#pragma unroll
        for (int kk = 0; kk < 32; ++kk) {
            float w = w2s[(k0 + kk) * 32 + c];
#pragma unroll
            for (int r = 0; r < 8; ++r)
                acc[r] += hs[(rg + 8 * r) * 32 + kk] * w;
        }
    }
#pragma unroll
    for (int r = 0; r < 8; ++r) {
        int rw = rowbase + rg + 8 * r;
        if (rw < NV) g_qs[(size_t)rw * 32 + c] = acc[r];
    }
}

// ---------------- out: mean_j q[j] + s + b' --------------------------------
__global__ __launch_bounds__(256) void k_out(float* __restrict__ out)
{
    int t = threadIdx.x;
    int slot = t >> 4;
    int c = t & 15;
    int i = blockIdx.x * 16 + slot;
    if (i >= NV) return;
    int beg = g_off[i], end = g_off[i + 1];
    float acc = 0.f;
    for (int e = beg; e < end; ++e) {
        int s = g_srcs[e];
        acc += g_qs[(size_t)s * 32 + c];
    }
    int deg = end - beg;
    float inv = 1.0f / (float)(deg > 0 ? deg : 1);
    out[(size_t)i * 16 + c] = acc * inv + g_qs[(size_t)i * 32 + 16 + c] + g_bp[c];
}

// ---------------- launch ----------------------------------------------------
extern "C" void kernel_launch(void* const* d_in, const int* in_sizes, int n_in,
                              void* d_out, int out_size)
{
    const float* x   = (const float*)d_in[0];
    const int*   ei  = (const int*)d_in[1];   // int32 [2,E]
    const float* W1l = (const float*)d_in[2];
    const float* b1  = (const float*)d_in[3];
    const float* W1r = (const float*)d_in[4];
    const float* W2l = (const float*)d_in[5];
    const float* b2  = (const float*)d_in[6];
    const float* W2r = (const float*)d_in[7];
    const float* Wc  = (const float*)d_in[8];
    const float* bc  = (const float*)d_in[9];
    float* out = (float*)d_out;

    k_prologue<<<24038, 256>>>(x, W1l, W1r, W2l, W2r, Wc, b2, bc, ei);  // 1
    k_scan<<<1, 1024>>>();                                              // 2
    k_gemm1_sc<<<5632, 128>>>(ei);                                      // 3 (gemm + scatter)
    k_agg1<<<NV, 128>>>(b1);                                            // 4
    k_gemm2<<<(NV + 63) / 64, 256>>>();                                 // 5
    k_out<<<(NV + 15) / 16, 256>>>(out);                                // 6
}

// round 13
// speedup vs baseline: 1.6007x; 1.0873x over previous
#include <cuda_runtime.h>
#include <cuda_bf16.h>
#include <mma.h>
#include <cstdint>

using namespace nvcuda;

#define NV  20000
#define NVP 20224            // padded rows (79 * 256) for unmasked wmma ld/st
#define EN  640000

// ---------------- scratch (device globals; no allocation allowed) ----------
__device__ int   g_deg[NV];
__device__ int   g_off[NV + 1];
__device__ int   g_cur[NV];
__device__ int   g_srcs[EN];
__device__ float g_w2[256 * 32];     // [K=256][N=32] = [W2l@Wc | W2r@Wc]
__device__ float g_bp[16];           // b2@Wc + bc
__device__ __nv_bfloat16 g_y[NVP * 256];   // x @ W1l  (bf16, padded)
__device__ float g_r[NVP * 256];     // x @ W1r   (padded)
__device__ float g_h[NV * 256];      // relu(mean(y) + r + b1)
__device__ float g_qs[NV * 32];      // [h@W2lWc | h@W2rWc]

__device__ __nv_bfloat16 g_xh[NVP * 256];    // bf16 hi of x (pad rows stay zero)
__device__ __nv_bfloat16 g_xl[NVP * 256];    // bf16 lo of x
__device__ __nv_bfloat16 g_whT[512 * 256];   // [N=512][K=256] bf16 hi of [W1l|W1r]
__device__ __nv_bfloat16 g_wlT[512 * 256];   // bf16 lo

// ---------------- merged prologue: split + prepwT + prepw2b + hist ----------
__global__ __launch_bounds__(256) void k_prologue(
    const float* __restrict__ x,
    const float* __restrict__ W1l, const float* __restrict__ W1r,
    const float* __restrict__ W2l, const float* __restrict__ W2r,
    const float* __restrict__ Wc,  const float* __restrict__ b2,
    const float* __restrict__ bc,  const int* __restrict__ ei)
{
    int b = blockIdx.x;
    int t = threadIdx.x;

    if (b < 20000) {
        int i = b * 256 + t;
        float v = x[i];
        __nv_bfloat16 h = __float2bfloat16(v);
        g_xh[i] = h;
        g_xl[i] = __float2bfloat16(v - __bfloat162float(h));
        if (i < NV) g_deg[i] = 0;
    } else if (b < 20512) {
        int i = (b - 20000) * 256 + t;     // 512*256
        int n = i >> 8, k = i & 255;
        float w = (n < 256) ? W1l[k * 256 + n] : W1r[k * 256 + (n - 256)];
        __nv_bfloat16 h = __float2bfloat16(w);
        g_whT[i] = h;
        g_wlT[i] = __float2bfloat16(w - __bfloat162float(h));
    } else if (b < 21538) {
        int w = ((b - 20512) * 256 + t) >> 5;
        int lane = t & 31;
        if (w < 8192) {
            int k = w >> 5, n = w & 31;
            const float* W = (n < 16) ? W2l : W2r;
            int c = n & 15;
            float acc = 0.f;
#pragma unroll
            for (int m = lane; m < 256; m += 32)
                acc += W[k * 256 + m] * Wc[m * 16 + c];
#pragma unroll
            for (int o = 16; o; o >>= 1) acc += __shfl_xor_sync(~0u, acc, o);
            if (lane == 0) g_w2[k * 32 + n] = acc;
        } else if (w < 8192 + 16) {
            int c = w - 8192;
            float acc = 0.f;
#pragma unroll
            for (int m = lane; m < 256; m += 32)
                acc += b2[m] * Wc[m * 16 + c];
#pragma unroll
            for (int o = 16; o; o >>= 1) acc += __shfl_xor_sync(~0u, acc, o);
            if (lane == 0) g_bp[c] = bc[c] + acc;
        }
    } else {
        int e = (b - 21538) * 256 + t;
        if (e < EN) {
            unsigned dst = (unsigned)ei[EN + e];
            if (dst < NV) atomicAdd(&g_deg[dst], 1);
        }
    }
}

// ---------------- CSR scan ---------------------------------------------------
__global__ void k_scan()
{
    __shared__ int part[1024];
    const int CH = 20;
    int t = threadIdx.x;
    int base = t * CH;
    int s = 0;
#pragma unroll
    for (int j = 0; j < CH; ++j) {
        int idx = base + j;
        if (idx < NV) s += g_deg[idx];
    }
    part[t] = s;
    __syncthreads();
    for (int off = 1; off < 1024; off <<= 1) {
        int v = 0;
        if (t >= off) v = part[t - off];
        __syncthreads();
        if (t >= off) part[t] += v;
        __syncthreads();
    }
    int run = (t == 0) ? 0 : part[t - 1];
#pragma unroll
    for (int j = 0; j < CH; ++j) {
        int idx = base + j;
        if (idx < NV) {
            g_off[idx] = run;
            g_cur[idx] = run;
            run += g_deg[idx];
        }
    }
    if (t == 0) g_off[NV] = EN;
}

// ---------------- gemm1 (wmma, warp tile 64x64) + scatter (merged) ----------
#define LDB 264
__global__ __launch_bounds__(128) void k_gemm1_sc(const int* __restrict__ ei)
{
    __shared__ __align__(16) char smraw[64 * LDB * 2];   // 33792 B
    int t = threadIdx.x;
    int b = blockIdx.x;

    if (b >= 632) {
        // ---------------- scatter part ----------------
        int e = (b - 632) * 128 + t;
        unsigned src = (unsigned)ei[e];
        unsigned dst = (unsigned)ei[EN + e];
        if (dst < NV && src < NV) {
            int pos = atomicAdd(&g_cur[dst], 1);
            g_srcs[pos] = (int)src;
        }
        return;
    }

    // ---------------- gemm part ----------------
    __nv_bfloat16* bs = (__nv_bfloat16*)smraw;
    float* stg = (float*)smraw;

    int wid = t >> 5;
    int lane = t & 31;
    int bx = b & 7;                          // N tile 0..7
    int by = b >> 3;                         // M tile 0..78
    int nbase = bx * 64;
    int row = by * 256 + wid * 64;

    wmma::fragment<wmma::accumulator, 16, 16, 16, float> acc[4][4];
#pragma unroll
    for (int i = 0; i < 4; ++i)
#pragma unroll
        for (int j = 0; j < 4; ++j) wmma::fill_fragment(acc[i][j], 0.0f);

    wmma::fragment<wmma::matrix_a, 16, 16, 16, __nv_bfloat16, wmma::row_major> af[4];
    wmma::fragment<wmma::matrix_b, 16, 16, 16, __nv_bfloat16, wmma::col_major> bf;

    // ---- stage wh tile (64 rows x 256 cols bf16) ----
    for (int i = t; i < 64 * 32; i += 128) {
        int r = i >> 5, c = i & 31;
        *(uint4*)&bs[r * LDB + c * 8] =
            *(const uint4*)&g_whT[(size_t)(nbase + r) * 256 + c * 8];
    }
    __syncthreads();

    // pass 1: xh @ wh ; pass 2: xl @ wh
#pragma unroll 1
    for (int pass = 0; pass < 2; ++pass) {
        const __nv_bfloat16* Asrc = pass ? g_xl : g_xh;
#pragma unroll 1
        for (int k0 = 0; k0 < 256; k0 += 16) {
#pragma unroll
            for (int i = 0; i < 4; ++i)
                wmma::load_matrix_sync(af[i], Asrc + (size_t)(row + i * 16) * 256 + k0, 256);
#pragma unroll
            for (int j = 0; j < 4; ++j) {
                wmma::load_matrix_sync(bf, bs + (j * 16) * LDB + k0, LDB);
#pragma unroll
                for (int i = 0; i < 4; ++i)
                    wmma::mma_sync(acc[i][j], af[i], bf, acc[i][j]);
            }
        }
    }
    __syncthreads();

    // ---- stage wl tile ----
    for (int i = t; i < 64 * 32; i += 128) {
        int r = i >> 5, c = i & 31;
        *(uint4*)&bs[r * LDB + c * 8] =
            *(const uint4*)&g_wlT[(size_t)(nbase + r) * 256 + c * 8];
    }
    __syncthreads();

    // pass 3: xh @ wl
#pragma unroll 1
    for (int k0 = 0; k0 < 256; k0 += 16) {
#pragma unroll
        for (int i = 0; i < 4; ++i)
            wmma::load_matrix_sync(af[i], g_xh + (size_t)(row + i * 16) * 256 + k0, 256);
#pragma unroll
        for (int j = 0; j < 4; ++j) {
            wmma::load_matrix_sync(bf, bs + (j * 16) * LDB + k0, LDB);
#pragma unroll
            for (int i = 0; i < 4; ++i)
                wmma::mma_sync(acc[i][j], af[i], bf, acc[i][j]);
        }
    }
    __syncthreads();   // done reading bs; smem reused as fp32 staging

    if (bx < 4) {
        float* w = stg + wid * (16 * 64);
#pragma unroll
        for (int i = 0; i < 4; ++i) {
#pragma unroll
            for (int j = 0; j < 4; ++j)
                wmma::store_matrix_sync(w + j * 16, acc[i][j], 64, wmma::mem_row_major);
            __syncwarp();
#pragma unroll
            for (int rr = 0; rr < 16; ++rr) {
                float f0 = w[rr * 64 + 2 * lane];
                float f1 = w[rr * 64 + 2 * lane + 1];
                __nv_bfloat162 p = __floats2bfloat162_rn(f0, f1);
                *(__nv_bfloat162*)&g_y[(size_t)(row + i * 16 + rr) * 256 + nbase + 2 * lane] = p;
            }
            __syncwarp();
        }
    } else {
        float* dstbase = g_r + (size_t)row * 256 + (nbase - 256);
#pragma unroll
        for (int i = 0; i < 4; ++i)
#pragma unroll
            for (int j = 0; j < 4; ++j)
                wmma::store_matrix_sync(dstbase + (size_t)i * 16 * 256 + j * 16,
                                        acc[i][j], 256, wmma::mem_row_major);
    }
}

// ---------------- agg1 + relu: h = relu(mean_j y[j] + r + b1) ---------------
// WARP-per-vertex: lane owns 8 features (one LDG.128 per edge); indices are
// loaded coalesced once per 32 edges and broadcast via shfl. bf16 unpack is
// shift/mask ALU. Index clamped defensively.
__global__ __launch_bounds__(256) void k_agg1(const float* __restrict__ b1)
{
    int wv = threadIdx.x >> 5;
    int lane = threadIdx.x & 31;
    int i = blockIdx.x * 8 + wv;
    if (i >= NV) return;
    int beg = g_off[i], end = g_off[i + 1];

    float a0 = 0.f, a1 = 0.f, a2 = 0.f, a3 = 0.f;
    float a4 = 0.f, a5 = 0.f, a6 = 0.f, a7 = 0.f;
    const char* ybase = (const char*)g_y + lane * 16;

    for (int e = beg; e < end; e += 32) {
        int n = end - e;
        if (n > 32) n = 32;
        int myidx = 0;
        if (lane < n) {
            myidx = g_srcs[e + lane];
            if ((unsigned)myidx >= NV) myidx = 0;   // defensive clamp
        }
        if (n == 32) {
#pragma unroll
            for (int j = 0; j < 32; ++j) {
                int s = __shfl_sync(0xFFFFFFFFu, myidx, j);
                uint4 v = *(const uint4*)(ybase + (size_t)s * 512);
                a0 += __uint_as_float(v.x << 16);
                a1 += __uint_as_float(v.x & 0xFFFF0000u);
                a2 += __uint_as_float(v.y << 16);
                a3 += __uint_as_float(v.y & 0xFFFF0000u);
                a4 += __uint_as_float(v.z << 16);
                a5 += __uint_as_float(v.z & 0xFFFF0000u);
                a6 += __uint_as_float(v.w << 16);
                a7 += __uint_as_float(v.w & 0xFFFF0000u);
            }
        } else {
            for (int j = 0; j < n; ++j) {
                int s = __shfl_sync(0xFFFFFFFFu, myidx, j);
                uint4 v = *(const uint4*)(ybase + (size_t)s * 512);
                a0 += __uint_as_float(v.x << 16);
                a1 += __uint_as_float(v.x & 0xFFFF0000u);
                a2 += __uint_as_float(v.y << 16);
                a3 += __uint_as_float(v.y & 0xFFFF0000u);
                a4 += __uint_as_float(v.z << 16);
                a5 += __uint_as_float(v.z & 0xFFFF0000u);
                a6 += __uint_as_float(v.w << 16);
                a7 += __uint_as_float(v.w & 0xFFFF0000u);
            }
        }
    }

    int deg = end - beg;
    float inv = 1.0f / (float)(deg > 0 ? deg : 1);
    const float4* rb = (const float4*)(g_r + (size_t)i * 256 + lane * 8);
    float4 r0 = rb[0], r1 = rb[1];
    const float4* bb = (const float4*)(b1 + lane * 8);
    float4 b0 = bb[0], b1v = bb[1];
    float4 h0, h1;
    h0.x = fmaxf(a0 * inv + r0.x + b0.x, 0.f);
    h0.y = fmaxf(a1 * inv + r0.y + b0.y, 0.f);
    h0.z = fmaxf(a2 * inv + r0.z + b0.z, 0.f);
    h0.w = fmaxf(a3 * inv + r0.w + b0.w, 0.f);
    h1.x = fmaxf(a4 * inv + r1.x + b1v.x, 0.f);
    h1.y = fmaxf(a5 * inv + r1.y + b1v.y, 0.f);
    h1.z = fmaxf(a6 * inv + r1.z + b1v.z, 0.f);
    h1.w = fmaxf(a7 * inv + r1.w + b1v.w, 0.f);
    float4* hd = (float4*)(g_h + (size_t)i * 256 + lane * 8);
    hd[0] = h0;
    hd[1] = h1;
}

// ---------------- GEMM2: g_qs = h @ g_w2  (M=20000, N=32, K=256) ------------
__global__ __launch_bounds__(256) void k_gemm2()
{
    __shared__ float w2s[256 * 32];
    __shared__ float hs[64 * 32];
    int t = threadIdx.x;
    for (int i = t; i < 256 * 32; i += 256) w2s[i] = g_w2[i];

    int rowbase = blockIdx.x * 64;
    int c = t & 31, rg = t >> 5;
    float acc[8];
#pragma unroll
    for (int r = 0; r < 8; ++r) acc[r] = 0.f;

    for (int k0 = 0; k0 < 256; k0 += 32) {
        __syncthreads();
        for (int i = t; i < 64 * 32; i += 256) {
            int rr = i >> 5, kk = i & 31;
            int rw = rowbase + rr;
            if (rw >= NV) rw = NV - 1;
            hs[i] = g_h[(size_t)rw * 256 + k0 + kk];
        }
        __syncthreads();
#pragma unroll
        for (int kk = 0; kk < 32; ++kk) {
            float w = w2s[(k0 + kk) * 32 + c];
#pragma unroll
            for (int r = 0; r < 8; ++r)
                acc[r] += hs[(rg + 8 * r) * 32 + kk] * w;
        }
    }
#pragma unroll
    for (int r = 0; r < 8; ++r) {
        int rw = rowbase + rg + 8 * r;
        if (rw < NV) g_qs[(size_t)rw * 32 + c] = acc[r];
    }
}

// ---------------- out: mean_j q[j] + s + b' --------------------------------
__global__ __launch_bounds__(256) void k_out(float* __restrict__ out)
{
    int t = threadIdx.x;
    int slot = t >> 4;
    int c = t & 15;
    int i = blockIdx.x * 16 + slot;
    if (i >= NV) return;
    int beg = g_off[i], end = g_off[i + 1];
    float acc = 0.f;
    for (int e = beg; e < end; ++e) {
        int s = g_srcs[e];
        acc += g_qs[(size_t)s * 32 + c];
    }
    int deg = end - beg;
    float inv = 1.0f / (float)(deg > 0 ? deg : 1);
    out[(size_t)i * 16 + c] = acc * inv + g_qs[(size_t)i * 32 + 16 + c] + g_bp[c];
}

// ---------------- launch ----------------------------------------------------
extern "C" void kernel_launch(void* const* d_in, const int* in_sizes, int n_in,
                              void* d_out, int out_size)
{
    const float* x   = (const float*)d_in[0];
    const int*   ei  = (const int*)d_in[1];   // int32 [2,E]
    const float* W1l = (const float*)d_in[2];
    const float* b1  = (const float*)d_in[3];
    const float* W1r = (const float*)d_in[4];
    const float* W2l = (const float*)d_in[5];
    const float* b2  = (const float*)d_in[6];
    const float* W2r = (const float*)d_in[7];
    const float* Wc  = (const float*)d_in[8];
    const float* bc  = (const float*)d_in[9];
    float* out = (float*)d_out;

    k_prologue<<<24038, 256>>>(x, W1l, W1r, W2l, W2r, Wc, b2, bc, ei);  // 1
    k_scan<<<1, 1024>>>();                                              // 2
    k_gemm1_sc<<<5632, 128>>>(ei);                                      // 3 (gemm + scatter)
    k_agg1<<<2500, 256>>>(b1);                                          // 4
    k_gemm2<<<(NV + 63) / 64, 256>>>();                                 // 5
    k_out<<<(NV + 15) / 16, 256>>>(out);                                // 6
}